// round 16
// baseline (speedup 1.0000x reference)
#include <cuda_runtime.h>

#define EPS 1e-8f
typedef unsigned long long ull;

constexpr int RS = 1184;                 // img row stride (floats), ≡0 mod 32
// img addr: r*RS + 4*(r/6) + k + 4*(k/32)

constexpr int OFF_ATT = 42656;           // ATT/A2 in-place region: ci*1584 + r*44 + l
constexpr int OFF_W1  = 48992;
constexpr int OFF_B1v = OFF_W1 + 256;
constexpr int OFF_W2S = OFF_B1v + 8;
constexpr int OFF_B2S = OFF_W2S + 8;
constexpr int OFF_RED = OFF_B2S + 4;
constexpr int SMEM_FLOATS = OFF_RED + 172;      // 49440
constexpr int SMEM_BYTES  = SMEM_FLOATS * 4;    // 197,760 B -> ~30 KB L1D left

__device__ float g_cos[1024 * 5120];     // per-block cosine scratch (L2-resident)

__device__ __forceinline__ ull dup2(float a) {
    ull r; asm("mov.b64 %0, {%1, %1};" : "=l"(r) : "f"(a)); return r;
}
__device__ __forceinline__ void f2(ull& d, ull a, ull b) {
    asm("fma.rn.f32x2 %0, %1, %2, %0;" : "+l"(d) : "l"(a), "l"(b));
}
__device__ __forceinline__ void up(ull v, float& lo, float& hi) {
    asm("mov.b64 {%0, %1}, %2;" : "=f"(lo), "=f"(hi) : "l"(v));
}

__global__ __launch_bounds__(384, 1)
void tg_kernel(const float* __restrict__ images, const float* __restrict__ captions,
               const int* __restrict__ cap_lens, const float* __restrict__ rare,
               const float* __restrict__ v1, const float* __restrict__ g1, const float* __restrict__ b1,
               const float* __restrict__ v2, const float* __restrict__ g2, const float* __restrict__ b2,
               const int* __restrict__ lam_p, float* __restrict__ out)
{
    extern __shared__ float sm[];
    const int tid = threadIdx.x;
    const int img = blockIdx.x;
    const int c0  = blockIdx.y * 4;
    const int bl  = blockIdx.y * 64 + blockIdx.x;

    // ---- preamble: image -> SMEM, RS=1184 + per-6-row-block skew + per-32-k skew ----
    {
        const float4* g4 = (const float4*)(images + (size_t)img * 36 * 1024);
        for (int i = tid; i < 9216; i += 384) {
            int r = i >> 8, kf = (i & 255) * 4;
            *(float4*)(sm + r * RS + 4 * (r / 6) + kf + 4 * (kf >> 5)) = g4[i];
        }
    }
    if (tid < 8) {
        int j = tid; float s = 0.f;
        for (int n = 0; n < 32; n++) { float v = v1[j * 32 + n]; s += v * v; }
        float inv = g1[j] / sqrtf(s);
        for (int n = 0; n < 32; n++) sm[OFF_W1 + j * 32 + n] = v1[j * 32 + n] * inv;
        sm[OFF_B1v + j] = b1[j];
    }
    if (tid == 8) {
        float w2s[8] = {0,0,0,0,0,0,0,0}; float b2s = 0.f;
        for (int k = 0; k < 6; k++) {
            float s = 0.f;
            for (int j = 0; j < 8; j++) { float v = v2[k * 8 + j]; s += v * v; }
            float inv = g2[k] / sqrtf(s);
            for (int j = 0; j < 8; j++) w2s[j] += v2[k * 8 + j] * inv;
            b2s += b2[k];
        }
        for (int j = 0; j < 8; j++) sm[OFF_W2S + j] = w2s[j];
        sm[OFF_B2S] = b2s;
    }
    const float lam = (float)(*lam_p);

    // Phase A map: khalf x [lg (slow) x capi x rg (fast)]
    const int khalf = tid / 192, t2 = tid % 192;
    const int lg = t2 / 24, r3 = t2 % 24, capi = r3 / 6, rg = r3 % 6;
    const int lg5 = lg * 5;
    const int mylen = cap_lens[c0 + capi];
    const bool actA = (lg5 < mylen);

    ull acc[6][5];
    #pragma unroll
    for (int q = 0; q < 6; q++)
        #pragma unroll
        for (int j = 0; j < 5; j++) acc[q][j] = 0ull;

    const float* ibase = sm + rg * (6 * RS) + 4 * rg + khalf * 16;
    const float* capgA = captions + (size_t)(c0 + capi) * 40960 + lg5 * 1024 + khalf * 16;

    __syncthreads();   // img resident

    // ========== Phase A: captions direct from global; drift bounded every 2 kc ==========
    #pragma unroll 2
    for (int kc = 0; kc < 32; kc++) {
        if (actA) {
            const float* ib = ibase + kc * 36;
            const float* cg = capgA + kc * 32;
            #pragma unroll
            for (int k4 = 0; k4 < 16; k4 += 4) {
                ulonglong2 I[6], C[5];
                #pragma unroll
                for (int q = 0; q < 6; q++) I[q] = *(const ulonglong2*)(ib + q * RS + k4);
                #pragma unroll
                for (int j = 0; j < 5; j++) C[j] = *(const ulonglong2*)(cg + j * 1024 + k4);
                #pragma unroll
                for (int q = 0; q < 6; q++)
                    #pragma unroll
                    for (int j = 0; j < 5; j++) {
                        f2(acc[q][j], I[q].x, C[j].x);
                        f2(acc[q][j], I[q].y, C[j].y);
                    }
            }
        }
        if ((kc & 1) == 1) __syncthreads();   // keep all warps in a ~40 KB caption window
    }

    // ---- epilogue: khalf reduction through ATT (stride 44), leaky-relu + mask ----
    {
        float* base = sm + OFF_ATT + capi * 1584;
        if (khalf) {
            #pragma unroll
            for (int q = 0; q < 6; q++)
                #pragma unroll
                for (int j = 0; j < 5; j++) {
                    float lo, hi; up(acc[q][j], lo, hi);
                    base[(rg * 6 + q) * 44 + lg5 + j] = lo + hi;
                }
        }
        __syncthreads();
        if (!khalf) {
            #pragma unroll
            for (int q = 0; q < 6; q++)
                #pragma unroll
                for (int j = 0; j < 5; j++) {
                    float lo, hi; up(acc[q][j], lo, hi);
                    int w = lg5 + j;
                    float v = lo + hi + base[(rg * 6 + q) * 44 + w];
                    v = (v > 0.f ? v : 0.1f * v);
                    base[(rg * 6 + q) * 44 + w] = (w < mylen) ? v : 0.f;
                }
        }
    }
    __syncthreads();

    // ===== B1: l2 norm over words per region =====
    if (tid < 144) {
        int ci = tid / 36, r = tid % 36;
        float* row = sm + OFF_ATT + ci * 1584 + r * 44;
        float s = 0.f;
        #pragma unroll 8
        for (int l = 0; l < 40; l++) { float v = row[l]; s += v * v; }
        float inv = 1.f / (sqrtf(s) + EPS);
        #pragma unroll 8
        for (int l = 0; l < 40; l++) row[l] *= inv;
    }
    __syncthreads();

    // ===== B2: softmax over regions, IN-PLACE (column l private per thread) =====
    if (tid < 160) {
        int ci = tid / 40, l = tid % 40;
        int len = cap_lens[c0 + ci];
        float* base = sm + OFF_ATT + ci * 1584;
        if (l < len) {
            float e[36]; float ssum = 0.f;
            #pragma unroll
            for (int r = 0; r < 36; r++) { e[r] = __expf(base[r * 44 + l] * lam); ssum += e[r]; }
            float inv = 1.f / ssum;
            #pragma unroll
            for (int r = 0; r < 36; r++) base[r * 44 + l] = e[r] * inv;
        } else {
            #pragma unroll
            for (int r = 0; r < 36; r++) base[r * 44 + l] = 0.f;
        }
    }
    __syncthreads();

    // ===== Phase C: per-warp (ci, 4-word group), lane = nbl; whole-warp skip =====
    {
        const int warp = tid >> 5, nbl = tid & 31;
        #pragma unroll 1
        for (int g = warp; g < 40; g += 12) {
            const int ci = g / 10, wgC = g % 10;
            const int w0 = wgC * 4;
            const int len = cap_lens[c0 + ci];
            if (w0 >= len) continue;
            const float* A2 = sm + OFF_ATT + ci * 1584 + w0;
            const float* capg = captions + (((size_t)(c0 + ci) * 40 + w0) << 10);
            float W12[4] = {0,0,0,0}, CN[4] = {0,0,0,0}, QN[4] = {0,0,0,0};
            #pragma unroll
            for (int h = 0; h < 2; h++) {
                ull wc[4][8];
                #pragma unroll
                for (int wd = 0; wd < 4; wd++)
                    #pragma unroll
                    for (int e = 0; e < 8; e++) wc[wd][e] = 0ull;
                #pragma unroll 1
                for (int rb = 0; rb < 6; rb++) {
                    const float* imgb = sm + rb * (6 * RS) + 4 * rb + nbl * 36 + h * 16;
                    const float* a2b = A2 + rb * (6 * 44);
                    #pragma unroll
                    for (int q = 0; q < 6; q++) {
                        float4 av = *(const float4*)(a2b + q * 44);
                        ull d0 = dup2(av.x), d1 = dup2(av.y), d2 = dup2(av.z), d3 = dup2(av.w);
                        const ulonglong2* ip = (const ulonglong2*)(imgb + q * RS);
                        ulonglong2 q0 = ip[0], q1 = ip[1], q2 = ip[2], q3 = ip[3];
                        f2(wc[0][0], d0, q0.x); f2(wc[0][1], d0, q0.y);
                        f2(wc[0][2], d0, q1.x); f2(wc[0][3], d0, q1.y);
                        f2(wc[0][4], d0, q2.x); f2(wc[0][5], d0, q2.y);
                        f2(wc[0][6], d0, q3.x); f2(wc[0][7], d0, q3.y);
                        f2(wc[1][0], d1, q0.x); f2(wc[1][1], d1, q0.y);
                        f2(wc[1][2], d1, q1.x); f2(wc[1][3], d1, q1.y);
                        f2(wc[1][4], d1, q2.x); f2(wc[1][5], d1, q2.y);
                        f2(wc[1][6], d1, q3.x); f2(wc[1][7], d1, q3.y);
                        f2(wc[2][0], d2, q0.x); f2(wc[2][1], d2, q0.y);
                        f2(wc[2][2], d2, q1.x); f2(wc[2][3], d2, q1.y);
                        f2(wc[2][4], d2, q2.x); f2(wc[2][5], d2, q2.y);
                        f2(wc[2][6], d2, q3.x); f2(wc[2][7], d2, q3.y);
                        f2(wc[3][0], d3, q0.x); f2(wc[3][1], d3, q0.y);
                        f2(wc[3][2], d3, q1.x); f2(wc[3][3], d3, q1.y);
                        f2(wc[3][4], d3, q2.x); f2(wc[3][5], d3, q2.y);
                        f2(wc[3][6], d3, q3.x); f2(wc[3][7], d3, q3.y);
                    }
                }
                #pragma unroll
                for (int wd = 0; wd < 4; wd++) {
                    const float4* q4 = (const float4*)(capg + wd * 1024 + nbl * 32 + h * 16);
                    float4 qa = q4[0], qb = q4[1], qc = q4[2], qd = q4[3];
                    float lo, hi;
                    up(wc[wd][0], lo, hi); W12[wd] += lo * qa.x + hi * qa.y; CN[wd] += lo * lo + hi * hi; QN[wd] += qa.x * qa.x + qa.y * qa.y;
                    up(wc[wd][1], lo, hi); W12[wd] += lo * qa.z + hi * qa.w; CN[wd] += lo * lo + hi * hi; QN[wd] += qa.z * qa.z + qa.w * qa.w;
                    up(wc[wd][2], lo, hi); W12[wd] += lo * qb.x + hi * qb.y; CN[wd] += lo * lo + hi * hi; QN[wd] += qb.x * qb.x + qb.y * qb.y;
                    up(wc[wd][3], lo, hi); W12[wd] += lo * qb.z + hi * qb.w; CN[wd] += lo * lo + hi * hi; QN[wd] += qb.z * qb.z + qb.w * qb.w;
                    up(wc[wd][4], lo, hi); W12[wd] += lo * qc.x + hi * qc.y; CN[wd] += lo * lo + hi * hi; QN[wd] += qc.x * qc.x + qc.y * qc.y;
                    up(wc[wd][5], lo, hi); W12[wd] += lo * qc.z + hi * qc.w; CN[wd] += lo * lo + hi * hi; QN[wd] += qc.z * qc.z + qc.w * qc.w;
                    up(wc[wd][6], lo, hi); W12[wd] += lo * qd.x + hi * qd.y; CN[wd] += lo * lo + hi * hi; QN[wd] += qd.x * qd.x + qd.y * qd.y;
                    up(wc[wd][7], lo, hi); W12[wd] += lo * qd.z + hi * qd.w; CN[wd] += lo * lo + hi * hi; QN[wd] += qd.z * qd.z + qd.w * qd.w;
                }
            }
            #pragma unroll
            for (int wd = 0; wd < 4; wd++)
                g_cos[(size_t)bl * 5120 + ci * 1280 + (w0 + wd) * 32 + nbl] =
                    W12[wd] / fmaxf(sqrtf(CN[wd]) * sqrtf(QN[wd]), EPS);
        }
    }
    __syncthreads();

    // ===== Phase D: weight-normed MLP + masked mean (cos from global scratch) =====
    if (tid < 160) {
        int ci = tid / 40, l = tid % 40;
        int len = cap_lens[c0 + ci];
        float res = 0.f;
        if (l < len) {
            const float* rr = rare + ((size_t)(c0 + ci) * 40 + l) * 32;
            const float* cb = g_cos + (size_t)bl * 5120 + ci * 1280 + l * 32;
            float x[32];
            #pragma unroll
            for (int n = 0; n < 32; n++) x[n] = cb[n] + 0.4f * rr[n];
            float persum = sm[OFF_B2S];
            #pragma unroll
            for (int j = 0; j < 8; j++) {
                float hsum = sm[OFF_B1v + j];
                const float* wr = sm + OFF_W1 + j * 32;
                #pragma unroll
                for (int n = 0; n < 32; n++) hsum = fmaf(x[n], wr[n], hsum);
                persum = fmaf(tanhf(hsum), sm[OFF_W2S + j], persum);
            }
            res = persum;
        }
        sm[OFF_RED + tid] = res;
    }
    __syncthreads();
    if (tid < 4) {
        int len = cap_lens[c0 + tid];
        float s = 0.f;
        for (int l = 0; l < len; l++) s += sm[OFF_RED + tid * 40 + l];
        out[(size_t)img * 64 + (c0 + tid)] = s / (float)(len * 6);
    }
}

extern "C" void kernel_launch(void* const* d_in, const int* in_sizes, int n_in,
                              void* d_out, int out_size) {
    const float* images   = (const float*)d_in[0];
    const float* captions = (const float*)d_in[1];
    const int*   cap_lens = (const int*)d_in[2];
    const float* rare     = (const float*)d_in[3];
    const float* v1       = (const float*)d_in[4];
    const float* g1       = (const float*)d_in[5];
    const float* b1       = (const float*)d_in[6];
    const float* v2       = (const float*)d_in[7];
    const float* g2       = (const float*)d_in[8];
    const float* b2       = (const float*)d_in[9];
    const int*   lam      = (const int*)d_in[12];
    float* out = (float*)d_out;

    cudaFuncSetAttribute(tg_kernel, cudaFuncAttributeMaxDynamicSharedMemorySize, SMEM_BYTES);
    tg_kernel<<<dim3(64, 16, 1), 384, SMEM_BYTES>>>(
        images, captions, cap_lens, rare, v1, g1, b1, v2, g2, b2, lam, out);
}